// round 2
// baseline (speedup 1.0000x reference)
#include <cuda_runtime.h>
#include <cuda_bf16.h>

// Scratch (allocation-free rule: __device__ globals)
// t1: (40, 256, 256) fp32 = 10.5 MB
// t2: (40, 768, 256) fp32 = 31.5 MB ; row index of t2 viewed as (30720,256) == vocab id
__device__ float g_t1[40 * 256 * 256];
__device__ float g_t2[40 * 768 * 256];

// ---------------------------------------------------------------------------
// Kernel 1: t1[i][b][c] = sum_a f0[i][a] * core[a][b][c]
// One thread per bc index (65536 total); each thread produces all 40 i outputs.
// core is read exactly once; f0 staged in smem.
// ---------------------------------------------------------------------------
__global__ void k_t1(const float* __restrict__ core, const float* __restrict__ f0) {
    __shared__ float sf0[40 * 40];
    const int tid = threadIdx.x;
    for (int idx = tid; idx < 1600; idx += blockDim.x) sf0[idx] = f0[idx];
    __syncthreads();

    const int bc = blockIdx.x * blockDim.x + tid;   // 0..65535
    float acc[40];
#pragma unroll
    for (int i = 0; i < 40; i++) acc[i] = 0.0f;

    for (int a = 0; a < 40; a++) {
        const float v = core[a * 65536 + bc];
#pragma unroll
        for (int i = 0; i < 40; i++) acc[i] += sf0[i * 40 + a] * v;
    }
#pragma unroll
    for (int i = 0; i < 40; i++) g_t1[i * 65536 + bc] = acc[i];
}

// ---------------------------------------------------------------------------
// Kernel 2: for each i in [0,40): t2_i (768x256) = f1 (768x256) @ t1_i (256x256)
// Standard smem-tiled fp32 GEMM. BM=BN=64, BK=16, 256 threads, 4x4 per thread.
// A (f1) is K-contiguous; B (t1_i) is N-contiguous.
// ---------------------------------------------------------------------------
__global__ void k_t2(const float* __restrict__ f1) {
    const int i  = blockIdx.z;
    const int m0 = blockIdx.y * 64;   // j tile
    const int n0 = blockIdx.x * 64;   // c tile

    const float* __restrict__ A = f1;                   // 768 x 256 (row-major, K contig)
    const float* __restrict__ B = g_t1 + i * 65536;     // 256 x 256 (row-major, N contig)
    float* __restrict__ C = g_t2 + i * (768 * 256);

    __shared__ float As[16][65];   // [k][m], padded: conflict-free inner reads
    __shared__ float Bs[16][64];   // [k][n]

    const int tx = threadIdx.x, ty = threadIdx.y;      // 16 x 16
    const int tid = ty * 16 + tx;

    const int am  = tid >> 2;          // 0..63   row of A tile
    const int ak4 = (tid & 3) * 4;     // 0,4,8,12
    const int bk  = tid >> 4;          // 0..15   row of B tile
    const int bn4 = (tid & 15) * 4;

    float acc[4][4] = {};

    for (int k0 = 0; k0 < 256; k0 += 16) {
        const float4 av = *(const float4*)&A[(m0 + am) * 256 + k0 + ak4];
        As[ak4 + 0][am] = av.x;
        As[ak4 + 1][am] = av.y;
        As[ak4 + 2][am] = av.z;
        As[ak4 + 3][am] = av.w;
        *(float4*)&Bs[bk][bn4] = *(const float4*)&B[(k0 + bk) * 256 + n0 + bn4];
        __syncthreads();

#pragma unroll
        for (int kk = 0; kk < 16; kk++) {
            float a[4];
            float4 b4 = *(const float4*)&Bs[kk][tx * 4];
            const float b[4] = {b4.x, b4.y, b4.z, b4.w};
#pragma unroll
            for (int r = 0; r < 4; r++) a[r] = As[kk][ty * 4 + r];
#pragma unroll
            for (int r = 0; r < 4; r++)
#pragma unroll
                for (int c = 0; c < 4; c++) acc[r][c] += a[r] * b[c];
        }
        __syncthreads();
    }

#pragma unroll
    for (int r = 0; r < 4; r++) {
        float4 o = make_float4(acc[r][0], acc[r][1], acc[r][2], acc[r][3]);
        *(float4*)&C[(m0 + ty * 4 + r) * 256 + n0 + tx * 4] = o;
    }
}

// ---------------------------------------------------------------------------
// Kernel 3: out[n][k] = sum_c t2[ids[n]][c] * f2[k][c]
// Row-gathered TN GEMM: M=8192, N=768, K=256. Both operands K-contiguous.
// BM=BN=64, BK=16, 256 threads, 4x4 per thread.
// ---------------------------------------------------------------------------
__global__ void k_out(const int* __restrict__ ids, const float* __restrict__ f2,
                      float* __restrict__ out) {
    const int m0 = blockIdx.y * 64;   // n tile (output rows)
    const int n0 = blockIdx.x * 64;   // k tile (output cols)

    __shared__ float As[16][65];   // [c][n]
    __shared__ float Bs[16][65];   // [c][k]
    __shared__ int   srow[64];

    const int tx = threadIdx.x, ty = threadIdx.y;
    const int tid = ty * 16 + tx;

    if (tid < 64) srow[tid] = ids[m0 + tid];
    __syncthreads();

    const int am  = tid >> 2;          // 0..63
    const int ak4 = (tid & 3) * 4;     // 0,4,8,12

    const long arow = (long)srow[am] * 256;   // gathered t2 row base

    float acc[4][4] = {};

    for (int k0 = 0; k0 < 256; k0 += 16) {
        const float4 av = *(const float4*)&g_t2[arow + k0 + ak4];
        As[ak4 + 0][am] = av.x;
        As[ak4 + 1][am] = av.y;
        As[ak4 + 2][am] = av.z;
        As[ak4 + 3][am] = av.w;
        const float4 bv = *(const float4*)&f2[(n0 + am) * 256 + k0 + ak4];
        Bs[ak4 + 0][am] = bv.x;
        Bs[ak4 + 1][am] = bv.y;
        Bs[ak4 + 2][am] = bv.z;
        Bs[ak4 + 3][am] = bv.w;
        __syncthreads();

#pragma unroll
        for (int kk = 0; kk < 16; kk++) {
            float a[4], b[4];
#pragma unroll
            for (int r = 0; r < 4; r++) a[r] = As[kk][ty * 4 + r];
#pragma unroll
            for (int c = 0; c < 4; c++) b[c] = Bs[kk][tx * 4 + c];
#pragma unroll
            for (int r = 0; r < 4; r++)
#pragma unroll
                for (int c = 0; c < 4; c++) acc[r][c] += a[r] * b[c];
        }
        __syncthreads();
    }

#pragma unroll
    for (int r = 0; r < 4; r++) {
        float4 o = make_float4(acc[r][0], acc[r][1], acc[r][2], acc[r][3]);
        *(float4*)&out[(long)(m0 + ty * 4 + r) * 768 + n0 + tx * 4] = o;
    }
}

// ---------------------------------------------------------------------------
// Inputs (metadata order): 0=x (unused), 1=ids (8192 i32), 2=core (40*256*256),
//                          3=f0 (40*40), 4=f1 (768*256), 5=f2 (768*256)
// Output: 8192 x 768 fp32
// ---------------------------------------------------------------------------
extern "C" void kernel_launch(void* const* d_in, const int* in_sizes, int n_in,
                              void* d_out, int out_size) {
    const int*   ids  = (const int*)d_in[1];
    const float* core = (const float*)d_in[2];
    const float* f0   = (const float*)d_in[3];
    const float* f1   = (const float*)d_in[4];
    const float* f2   = (const float*)d_in[5];
    float*       out  = (float*)d_out;

    // Kernel 1: 65536 bc positions, 256 threads/block
    k_t1<<<256, 256>>>(core, f0);

    // Kernel 2: grid (c-tiles=4, j-tiles=12, i=40)
    {
        dim3 grid(256 / 64, 768 / 64, 40);
        dim3 block(16, 16);
        k_t2<<<grid, block>>>(f1);
    }

    // Kernel 3: grid (k-tiles=12, n-tiles=128)
    {
        dim3 grid(768 / 64, 8192 / 64);
        dim3 block(16, 16);
        k_out<<<grid, block>>>(ids, f2, out);
    }
}

// round 6
// speedup vs baseline: 1.5402x; 1.5402x over previous
#include <cuda_runtime.h>
#include <cuda_bf16.h>
#include <mma.h>

using namespace nvcuda;

// Scratch (allocation-free rule: __device__ globals)
// t1: (40, 256, 256) fp32 ; t2: (40, 768, 256) fp32
// Row index of t2 viewed as (30720, 256) == vocab id.
__device__ float g_t1[40 * 256 * 256];
__device__ float g_t2[40 * 768 * 256];

// ---------------------------------------------------------------------------
// Kernel 1: t1[i][b][c] = sum_a f0[i][a] * core[a][b][c]
// Split i-dim into 2 groups of 20 for occupancy (grid 512 blocks).
// ---------------------------------------------------------------------------
__global__ void k_t1(const float* __restrict__ core, const float* __restrict__ f0) {
    __shared__ float sf0[20 * 40];
    const int tid = threadIdx.x;
    const int ig  = blockIdx.y;              // i-group: 0 or 1
    for (int idx = tid; idx < 800; idx += blockDim.x) sf0[idx] = f0[ig * 800 + idx];
    __syncthreads();

    const int bc = blockIdx.x * blockDim.x + tid;   // 0..65535
    float acc[20];
#pragma unroll
    for (int i = 0; i < 20; i++) acc[i] = 0.0f;

    for (int a = 0; a < 40; a++) {
        const float v = core[a * 65536 + bc];
#pragma unroll
        for (int i = 0; i < 20; i++) acc[i] += sf0[i * 40 + a] * v;
    }
#pragma unroll
    for (int i = 0; i < 20; i++) g_t1[(ig * 20 + i) * 65536 + bc] = acc[i];
}

// ---------------------------------------------------------------------------
// Kernel 2 (TF32 wmma): for each i: t2_i (768x256) = f1 (768x256) @ t1_i (256x256)
// A = f1 row-major (m,k); B = t1_i row-major (k,n).
// Tile BM=64, BN=64, BK=32. 8 warps as 4(M) x 2(N); warp tile 16x32.
// ---------------------------------------------------------------------------
__global__ void k_t2(const float* __restrict__ f1) {
    const int i  = blockIdx.z;
    const int m0 = blockIdx.y * 64;
    const int n0 = blockIdx.x * 64;

    const float* __restrict__ A = f1;
    const float* __restrict__ B = g_t1 + i * 65536;
    float* __restrict__ C = g_t2 + i * (768 * 256);

    __shared__ __align__(16) float As[64][40];   // [m][k], ld=40
    __shared__ __align__(16) float Bs[32][72];   // [k][n], ld=72

    const int tid    = threadIdx.x;
    const int warpId = tid >> 5;
    const int wm     = warpId >> 1;      // 0..3
    const int wn     = warpId & 1;       // 0..1

    wmma::fragment<wmma::accumulator, 16, 16, 8, float> c[2];
    wmma::fill_fragment(c[0], 0.0f);
    wmma::fill_fragment(c[1], 0.0f);

    for (int k0 = 0; k0 < 256; k0 += 32) {
        // stage A: 64x32 (512 float4, 2 per thread)
#pragma unroll
        for (int rep = 0; rep < 2; rep++) {
            int idx = tid + rep * 256;
            int r = idx >> 3, c4 = (idx & 7) * 4;
            *(float4*)&As[r][c4] = *(const float4*)&A[(m0 + r) * 256 + k0 + c4];
        }
        // stage B: 32x64 (512 float4)
#pragma unroll
        for (int rep = 0; rep < 2; rep++) {
            int idx = tid + rep * 256;
            int r = idx >> 4, c4 = (idx & 15) * 4;
            *(float4*)&Bs[r][c4] = *(const float4*)&B[(k0 + r) * 256 + n0 + c4];
        }
        __syncthreads();

#pragma unroll
        for (int kk = 0; kk < 32; kk += 8) {
            wmma::fragment<wmma::matrix_a, 16, 16, 8, wmma::precision::tf32, wmma::row_major> a;
            wmma::load_matrix_sync(a, &As[wm * 16][kk], 40);
#pragma unroll
            for (int t = 0; t < a.num_elements; t++) a.x[t] = wmma::__float_to_tf32(a.x[t]);
#pragma unroll
            for (int f = 0; f < 2; f++) {
                wmma::fragment<wmma::matrix_b, 16, 16, 8, wmma::precision::tf32, wmma::row_major> b;
                wmma::load_matrix_sync(b, &Bs[kk][wn * 32 + f * 16], 72);
#pragma unroll
                for (int t = 0; t < b.num_elements; t++) b.x[t] = wmma::__float_to_tf32(b.x[t]);
                wmma::mma_sync(c[f], a, b, c[f]);
            }
        }
        __syncthreads();
    }

#pragma unroll
    for (int f = 0; f < 2; f++)
        wmma::store_matrix_sync(&C[(m0 + wm * 16) * 256 + n0 + wn * 32 + f * 16],
                                c[f], 256, wmma::mem_row_major);
}

// ---------------------------------------------------------------------------
// Kernel 3 (TF32 wmma): out[n][k_h] = sum_c t2[ids[n]][c] * f2[k_h][c]
// Gathered TN GEMM: M=8192, N=768, K=256.
// A = gathered t2 rows, row-major (m,k); B = f2 (n,k) row-major -> wmma col_major.
// ---------------------------------------------------------------------------
__global__ void k_out(const int* __restrict__ ids, const float* __restrict__ f2,
                      float* __restrict__ out) {
    const int m0 = blockIdx.y * 64;   // output rows (tokens)
    const int n0 = blockIdx.x * 64;   // output cols (hidden)

    __shared__ __align__(16) float As[64][40];   // [m][k], ld=40
    __shared__ __align__(16) float Bs[64][40];   // [n][k], ld=40 (col_major frag)
    __shared__ int srow[64];

    const int tid    = threadIdx.x;
    const int warpId = tid >> 5;
    const int wm     = warpId >> 1;
    const int wn     = warpId & 1;

    if (tid < 64) srow[tid] = ids[m0 + tid];
    __syncthreads();

    wmma::fragment<wmma::accumulator, 16, 16, 8, float> c[2];
    wmma::fill_fragment(c[0], 0.0f);
    wmma::fill_fragment(c[1], 0.0f);

    for (int k0 = 0; k0 < 256; k0 += 32) {
        // stage A (gathered): 64x32
#pragma unroll
        for (int rep = 0; rep < 2; rep++) {
            int idx = tid + rep * 256;
            int r = idx >> 3, c4 = (idx & 7) * 4;
            long arow = (long)srow[r] * 256;
            *(float4*)&As[r][c4] = *(const float4*)&g_t2[arow + k0 + c4];
        }
        // stage B: f2 rows n0..n0+63, cols k0..k0+31
#pragma unroll
        for (int rep = 0; rep < 2; rep++) {
            int idx = tid + rep * 256;
            int r = idx >> 3, c4 = (idx & 7) * 4;
            *(float4*)&Bs[r][c4] = *(const float4*)&f2[(n0 + r) * 256 + k0 + c4];
        }
        __syncthreads();

#pragma unroll
        for (int kk = 0; kk < 32; kk += 8) {
            wmma::fragment<wmma::matrix_a, 16, 16, 8, wmma::precision::tf32, wmma::row_major> a;
            wmma::load_matrix_sync(a, &As[wm * 16][kk], 40);
#pragma unroll
            for (int t = 0; t < a.num_elements; t++) a.x[t] = wmma::__float_to_tf32(a.x[t]);
#pragma unroll
            for (int f = 0; f < 2; f++) {
                // col_major: element (k, n_local) at base[n_local*ld + k]
                wmma::fragment<wmma::matrix_b, 16, 16, 8, wmma::precision::tf32, wmma::col_major> b;
                wmma::load_matrix_sync(b, &Bs[wn * 32 + f * 16][kk], 40);
#pragma unroll
                for (int t = 0; t < b.num_elements; t++) b.x[t] = wmma::__float_to_tf32(b.x[t]);
                wmma::mma_sync(c[f], a, b, c[f]);
            }
        }
        __syncthreads();
    }

#pragma unroll
    for (int f = 0; f < 2; f++)
        wmma::store_matrix_sync(&out[(long)(m0 + wm * 16) * 768 + n0 + wn * 32 + f * 16],
                                c[f], 768, wmma::mem_row_major);
}

// ---------------------------------------------------------------------------
// Inputs: 0=x (unused), 1=ids, 2=core, 3=f0, 4=f1, 5=f2 ; out: 8192x768 fp32
// ---------------------------------------------------------------------------
extern "C" void kernel_launch(void* const* d_in, const int* in_sizes, int n_in,
                              void* d_out, int out_size) {
    const int*   ids  = (const int*)d_in[1];
    const float* core = (const float*)d_in[2];
    const float* f0   = (const float*)d_in[3];
    const float* f1   = (const float*)d_in[4];
    const float* f2   = (const float*)d_in[5];
    float*       out  = (float*)d_out;

    {
        dim3 grid(256, 2);
        k_t1<<<grid, 256>>>(core, f0);
    }
    {
        dim3 grid(256 / 64, 768 / 64, 40);
        k_t2<<<grid, 256>>>(f1);
    }
    {
        dim3 grid(768 / 64, 8192 / 64);
        k_out<<<grid, 256>>>(ids, f2, out);
    }
}

// round 8
// speedup vs baseline: 1.8020x; 1.1699x over previous
#include <cuda_runtime.h>
#include <cuda_bf16.h>
#include <mma.h>
#include <cstdint>

using namespace nvcuda;

// Scratch (__device__ globals; allocation-free rule)
__device__ float g_t1[40 * 256 * 256];   // tf32-rounded
__device__ float g_t2[40 * 768 * 256];   // tf32-rounded
__device__ float g_f1r[768 * 256];       // tf32-rounded f1
__device__ float g_f2r[768 * 256];       // tf32-rounded f2

__device__ __forceinline__ void cp16(void* s, const void* g) {
    unsigned int sa = (unsigned int)__cvta_generic_to_shared(s);
    asm volatile("cp.async.cg.shared.global [%0], [%1], 16;\n" :: "r"(sa), "l"(g));
}
#define CP_COMMIT() asm volatile("cp.async.commit_group;\n" ::: "memory")
#define CP_WAIT1()  asm volatile("cp.async.wait_group 1;\n" ::: "memory")
#define CP_WAIT0()  asm volatile("cp.async.wait_group 0;\n" ::: "memory")

// ---------------------------------------------------------------------------
// Round f1, f2 to tf32 once (so GEMM hot loops have no convert instructions).
// 49152 float4 per array; one float4 of each per thread.
// ---------------------------------------------------------------------------
__global__ void k_round(const float* __restrict__ f1, const float* __restrict__ f2) {
    int idx = blockIdx.x * blockDim.x + threadIdx.x;   // 0..49151
    float4 v = ((const float4*)f1)[idx];
    v.x = wmma::__float_to_tf32(v.x); v.y = wmma::__float_to_tf32(v.y);
    v.z = wmma::__float_to_tf32(v.z); v.w = wmma::__float_to_tf32(v.w);
    ((float4*)g_f1r)[idx] = v;
    v = ((const float4*)f2)[idx];
    v.x = wmma::__float_to_tf32(v.x); v.y = wmma::__float_to_tf32(v.y);
    v.z = wmma::__float_to_tf32(v.z); v.w = wmma::__float_to_tf32(v.w);
    ((float4*)g_f2r)[idx] = v;
}

// ---------------------------------------------------------------------------
// Kernel 1: t1[i][b][c] = sum_a f0[i][a] * core[a][b][c]  (store tf32-rounded)
// 4 i-groups of 10 -> grid 1024 blocks for occupancy.
// ---------------------------------------------------------------------------
__global__ void k_t1(const float* __restrict__ core, const float* __restrict__ f0) {
    __shared__ float sf0[10 * 40];
    const int tid = threadIdx.x;
    const int ig  = blockIdx.y;              // i-group: 0..3
    for (int idx = tid; idx < 400; idx += blockDim.x) sf0[idx] = f0[ig * 400 + idx];
    __syncthreads();

    const int bc = blockIdx.x * blockDim.x + tid;   // 0..65535
    float acc[10];
#pragma unroll
    for (int i = 0; i < 10; i++) acc[i] = 0.0f;

#pragma unroll 4
    for (int a = 0; a < 40; a++) {
        const float v = core[a * 65536 + bc];
#pragma unroll
        for (int i = 0; i < 10; i++) acc[i] += sf0[i * 40 + a] * v;
    }
#pragma unroll
    for (int i = 0; i < 10; i++)
        g_t1[(ig * 10 + i) * 65536 + bc] = wmma::__float_to_tf32(acc[i]);
}

// ---------------------------------------------------------------------------
// Kernel 2 (TF32, cp.async pipelined): t2_i (768x256) = f1 (768x256) @ t1_i (256x256)
// BM=128, BN=64, BK=16. 8 warps as 4(M)x2(N); warp tile 32x32 (c[2][2]).
// Inputs already tf32-rounded; epilogue stores tf32-rounded (feeds k_out).
// ---------------------------------------------------------------------------
__global__ void k_t2() {
    const int i  = blockIdx.z;
    const int m0 = blockIdx.y * 128;
    const int n0 = blockIdx.x * 64;

    const float* __restrict__ A = g_f1r;                // (m,k) row-major
    const float* __restrict__ B = g_t1 + i * 65536;     // (k,n) row-major
    float* __restrict__ C = g_t2 + i * (768 * 256);

    __shared__ __align__(16) float As[2][128][20];      // [m][k] ld=20
    __shared__ __align__(16) float Bs[2][16][68];       // [k][n] ld=68

    const int tid    = threadIdx.x;
    const int warpId = tid >> 5;
    const int wm     = warpId >> 1;      // 0..3 -> m offset wm*32
    const int wn     = warpId & 1;       // 0..1 -> n offset wn*32

    wmma::fragment<wmma::accumulator, 16, 16, 8, float> c[2][2];
#pragma unroll
    for (int r = 0; r < 2; r++)
#pragma unroll
        for (int f = 0; f < 2; f++) wmma::fill_fragment(c[r][f], 0.0f);

    const int ar  = (tid) >> 2;            // rows for A stage (2 chunks/thread)
    const int ac4 = (tid & 3) * 4;
    const int ar2 = (tid + 256) >> 2;
    const int br  = tid >> 4;              // 0..15
    const int bc4 = (tid & 15) * 4;

    // stage tile 0
    {
        cp16(&As[0][ar][ac4],  &A[(m0 + ar)  * 256 + ac4]);
        cp16(&As[0][ar2][ac4], &A[(m0 + ar2) * 256 + ac4]);
        cp16(&Bs[0][br][bc4],  &B[br * 256 + n0 + bc4]);
        CP_COMMIT();
    }

    for (int it = 0; it < 16; ++it) {
        const int buf = it & 1;
        if (it < 15) {
            const int k0 = (it + 1) * 16;
            const int nb = buf ^ 1;
            cp16(&As[nb][ar][ac4],  &A[(m0 + ar)  * 256 + k0 + ac4]);
            cp16(&As[nb][ar2][ac4], &A[(m0 + ar2) * 256 + k0 + ac4]);
            cp16(&Bs[nb][br][bc4],  &B[(k0 + br) * 256 + n0 + bc4]);
            CP_COMMIT();
            CP_WAIT1();
        } else {
            CP_WAIT0();
        }
        __syncthreads();

#pragma unroll
        for (int kk = 0; kk < 16; kk += 8) {
            wmma::fragment<wmma::matrix_a, 16, 16, 8, wmma::precision::tf32, wmma::row_major> a[2];
#pragma unroll
            for (int r = 0; r < 2; r++)
                wmma::load_matrix_sync(a[r], &As[buf][wm * 32 + r * 16][kk], 20);
#pragma unroll
            for (int f = 0; f < 2; f++) {
                wmma::fragment<wmma::matrix_b, 16, 16, 8, wmma::precision::tf32, wmma::row_major> b;
                wmma::load_matrix_sync(b, &Bs[buf][kk][wn * 32 + f * 16], 68);
#pragma unroll
                for (int r = 0; r < 2; r++) wmma::mma_sync(c[r][f], a[r], b, c[r][f]);
            }
        }
        __syncthreads();
    }

    // epilogue: round to tf32 (k_out consumes this) and store
#pragma unroll
    for (int r = 0; r < 2; r++)
#pragma unroll
        for (int f = 0; f < 2; f++) {
#pragma unroll
            for (int t = 0; t < c[r][f].num_elements; t++)
                c[r][f].x[t] = wmma::__float_to_tf32(c[r][f].x[t]);
            wmma::store_matrix_sync(&C[(m0 + wm * 32 + r * 16) * 256 + n0 + wn * 32 + f * 16],
                                    c[r][f], 256, wmma::mem_row_major);
        }
}

// ---------------------------------------------------------------------------
// Kernel 3 (TF32, cp.async pipelined, gathered): out[n][h] = sum_c t2[ids[n]][c]*f2[h][c]
// M=8192, N=768, K=256. BM=128, BN=64, BK=16. Warp tile 32x32.
// A = gathered t2 rows (row-major m,k); B = f2r (n,k) -> col_major fragment.
// ---------------------------------------------------------------------------
__global__ void k_out(const int* __restrict__ ids, float* __restrict__ out) {
    const int m0 = blockIdx.y * 128;   // token rows
    const int n0 = blockIdx.x * 64;    // hidden cols

    __shared__ __align__(16) float As[2][128][20];   // [m][k] ld=20
    __shared__ __align__(16) float Bs[2][64][20];    // [n][k] ld=20
    __shared__ int srow[128];

    const int tid    = threadIdx.x;
    const int warpId = tid >> 5;
    const int wm     = warpId >> 1;
    const int wn     = warpId & 1;

    if (tid < 128) srow[tid] = ids[m0 + tid];
    __syncthreads();

    wmma::fragment<wmma::accumulator, 16, 16, 8, float> c[2][2];
#pragma unroll
    for (int r = 0; r < 2; r++)
#pragma unroll
        for (int f = 0; f < 2; f++) wmma::fill_fragment(c[r][f], 0.0f);

    const int ar  = tid >> 2;            // A stage rows (2 chunks/thread)
    const int ac4 = (tid & 3) * 4;
    const int ar2 = (tid + 256) >> 2;
    const long arow  = (long)srow[ar]  * 256;
    const long arow2 = (long)srow[ar2] * 256;
    const int brr = tid >> 2;            // 0..63 (B stage: 1 chunk/thread)

    // stage tile 0
    {
        cp16(&As[0][ar][ac4],  &g_t2[arow  + ac4]);
        cp16(&As[0][ar2][ac4], &g_t2[arow2 + ac4]);
        cp16(&Bs[0][brr][ac4], &g_f2r[(n0 + brr) * 256 + ac4]);
        CP_COMMIT();
    }

    for (int it = 0; it < 16; ++it) {
        const int buf = it & 1;
        if (it < 15) {
            const int k0 = (it + 1) * 16;
            const int nb = buf ^ 1;
            cp16(&As[nb][ar][ac4],  &g_t2[arow  + k0 + ac4]);
            cp16(&As[nb][ar2][ac4], &g_t2[arow2 + k0 + ac4]);
            cp16(&Bs[nb][brr][ac4], &g_f2r[(n0 + brr) * 256 + k0 + ac4]);
            CP_COMMIT();
            CP_WAIT1();
        } else {
            CP_WAIT0();
        }
        __syncthreads();

#pragma unroll
        for (int kk = 0; kk < 16; kk += 8) {
            wmma::fragment<wmma::matrix_a, 16, 16, 8, wmma::precision::tf32, wmma::row_major> a[2];
#pragma unroll
            for (int r = 0; r < 2; r++)
                wmma::load_matrix_sync(a[r], &As[buf][wm * 32 + r * 16][kk], 20);
#pragma unroll
            for (int f = 0; f < 2; f++) {
                // col_major: element (k, n_local) at base[n_local*ld + k]
                wmma::fragment<wmma::matrix_b, 16, 16, 8, wmma::precision::tf32, wmma::col_major> b;
                wmma::load_matrix_sync(b, &Bs[buf][wn * 32 + f * 16][kk], 20);
#pragma unroll
                for (int r = 0; r < 2; r++) wmma::mma_sync(c[r][f], a[r], b, c[r][f]);
            }
        }
        __syncthreads();
    }

#pragma unroll
    for (int r = 0; r < 2; r++)
#pragma unroll
        for (int f = 0; f < 2; f++)
            wmma::store_matrix_sync(&out[(long)(m0 + wm * 32 + r * 16) * 768 + n0 + wn * 32 + f * 16],
                                    c[r][f], 768, wmma::mem_row_major);
}

// ---------------------------------------------------------------------------
// Inputs: 0=x (unused), 1=ids, 2=core, 3=f0, 4=f1, 5=f2 ; out: 8192x768 fp32
// ---------------------------------------------------------------------------
extern "C" void kernel_launch(void* const* d_in, const int* in_sizes, int n_in,
                              void* d_out, int out_size) {
    const int*   ids  = (const int*)d_in[1];
    const float* core = (const float*)d_in[2];
    const float* f0   = (const float*)d_in[3];
    const float* f1   = (const float*)d_in[4];
    const float* f2   = (const float*)d_in[5];
    float*       out  = (float*)d_out;

    k_round<<<192, 256>>>(f1, f2);
    {
        dim3 grid(256, 4);
        k_t1<<<grid, 256>>>(core, f0);
    }
    {
        dim3 grid(256 / 64, 768 / 128, 40);
        k_t2<<<grid, 256>>>();
    }
    {
        dim3 grid(768 / 64, 8192 / 128);
        k_out<<<grid, 256>>>(ids, out);
    }
}

// round 11
// speedup vs baseline: 4.6119x; 2.5594x over previous
#include <cuda_runtime.h>
#include <cuda_fp16.h>
#include <mma.h>
#include <cstdint>

using namespace nvcuda;

// ---------------------------------------------------------------------------
// Scratch (__device__ globals; allocation-free rule) — all fp16
// ---------------------------------------------------------------------------
__device__ __align__(16) __half g_t1h[40 * 256 * 256];   // [i][b][c]
__device__ __align__(16) __half g_t2h[40 * 768 * 256];   // [(i*768+j)][c]
__device__ __align__(16) __half g_f1h[768 * 256];        // [j][b]
__device__ __align__(16) __half g_f2h[768 * 256];        // [h][c]

__device__ __forceinline__ void cp16(void* s, const void* g) {
    unsigned int sa = (unsigned int)__cvta_generic_to_shared(s);
    asm volatile("cp.async.cg.shared.global [%0], [%1], 16;\n" :: "r"(sa), "l"(g));
}
#define CP_COMMIT() asm volatile("cp.async.commit_group;\n" ::: "memory")
#define CP_WAIT1()  asm volatile("cp.async.wait_group 1;\n" ::: "memory")
#define CP_WAIT0()  asm volatile("cp.async.wait_group 0;\n" ::: "memory")

// ---------------------------------------------------------------------------
// k_prep: f1, f2 -> fp16
// ---------------------------------------------------------------------------
__global__ void k_prep(const float* __restrict__ f1, const float* __restrict__ f2) {
    int idx = blockIdx.x * blockDim.x + threadIdx.x;   // 0..49151 (x4 floats)
    float4 v = ((const float4*)f1)[idx];
    __half2 a = __floats2half2_rn(v.x, v.y), b = __floats2half2_rn(v.z, v.w);
    ((__half2*)g_f1h)[idx * 2] = a; ((__half2*)g_f1h)[idx * 2 + 1] = b;
    v = ((const float4*)f2)[idx];
    a = __floats2half2_rn(v.x, v.y); b = __floats2half2_rn(v.z, v.w);
    ((__half2*)g_f2h)[idx * 2] = a; ((__half2*)g_f2h)[idx * 2 + 1] = b;
}

// ---------------------------------------------------------------------------
// k_t1: t1[i][b][c] = sum_a f0[i][a] * core[a][b][c]   (fp32 math, fp16 store)
// 4 i-groups of 10 -> grid (256, 4), 256 threads.
// ---------------------------------------------------------------------------
__global__ void k_t1(const float* __restrict__ core, const float* __restrict__ f0) {
    __shared__ float sf0[10 * 40];
    const int tid = threadIdx.x;
    const int ig  = blockIdx.y;
    for (int idx = tid; idx < 400; idx += blockDim.x) sf0[idx] = f0[ig * 400 + idx];
    __syncthreads();

    const int bc = blockIdx.x * blockDim.x + tid;   // 0..65535
    float acc[10];
#pragma unroll
    for (int i = 0; i < 10; i++) acc[i] = 0.0f;

#pragma unroll 4
    for (int a = 0; a < 40; a++) {
        const float v = core[a * 65536 + bc];
#pragma unroll
        for (int i = 0; i < 10; i++) acc[i] += sf0[i * 40 + a] * v;
    }
#pragma unroll
    for (int i = 0; i < 10; i++)
        g_t1h[(size_t)(ig * 10 + i) * 65536 + bc] = __float2half(acc[i]);
}

// ---------------------------------------------------------------------------
// k_t2 (fp16 wmma, cp.async pipelined): per i: t2_i (768x256) = f1 @ t1_i
// A = f1h (m,k) row-major; B = t1h_i (k,n) row-major. Output fp16.
// BM=128, BN=128, BK=32. 8 warps as 2(M) x 4(N); warp tile 64x32 (c[4][2]).
// ---------------------------------------------------------------------------
__global__ void k_t2() {
    const int n0 = blockIdx.x * 128;
    const int m0 = blockIdx.y * 128;
    const int i  = blockIdx.z;

    const __half* __restrict__ A = g_f1h;
    const __half* __restrict__ B = g_t1h + (size_t)i * 65536;
    __half* __restrict__ C = g_t2h + (size_t)i * (768 * 256);

    __shared__ __align__(16) __half As[2][128][40];    // [m][k] ld=40
    __shared__ __align__(16) __half Bs[2][32][136];    // [k][n] ld=136

    const int tid    = threadIdx.x;
    const int warpId = tid >> 5;
    const int wm     = warpId & 1;       // 0..1 -> m offset wm*64
    const int wn     = warpId >> 1;      // 0..3 -> n offset wn*32

    wmma::fragment<wmma::accumulator, 16, 16, 16, float> c[4][2];
#pragma unroll
    for (int r = 0; r < 4; r++)
#pragma unroll
        for (int f = 0; f < 2; f++) wmma::fill_fragment(c[r][f], 0.0f);

    // A staging: 128 rows x 32 halves (4x16B chunks/row) = 512 chunks, 2/thread
    const int arow = tid >> 1;                 // covers 0..127 over 2 reps
    const int ach  = (tid & 1) * 16;           // halves, two chunk pairs? no:
    // use explicit: idx = tid + rep*256; row = idx>>2; chunk halves = (idx&3)*8
    // B staging: 32 rows x 128 halves (16 chunks/row) = 512 chunks, 2/thread

#define STAGE_T2(bufi, k0)                                                              \
    do {                                                                                \
        _Pragma("unroll")                                                               \
        for (int rep = 0; rep < 2; rep++) {                                             \
            int idx = tid + rep * 256;                                                  \
            int r_ = idx >> 2, c_ = (idx & 3) * 8;                                      \
            cp16(&As[bufi][r_][c_], &A[(size_t)(m0 + r_) * 256 + (k0) + c_]);           \
        }                                                                               \
        _Pragma("unroll")                                                               \
        for (int rep = 0; rep < 2; rep++) {                                             \
            int idx = tid + rep * 256;                                                  \
            int r_ = idx >> 4, c_ = (idx & 15) * 8;                                     \
            cp16(&Bs[bufi][r_][c_], &B[(size_t)((k0) + r_) * 256 + n0 + c_]);           \
        }                                                                               \
        CP_COMMIT();                                                                    \
    } while (0)

    STAGE_T2(0, 0);

    for (int it = 0; it < 8; ++it) {
        const int buf = it & 1;
        if (it < 7) { STAGE_T2(buf ^ 1, (it + 1) * 32); CP_WAIT1(); }
        else        { CP_WAIT0(); }
        __syncthreads();

#pragma unroll
        for (int kk = 0; kk < 32; kk += 16) {
            wmma::fragment<wmma::matrix_a, 16, 16, 16, __half, wmma::row_major> a[4];
#pragma unroll
            for (int r = 0; r < 4; r++)
                wmma::load_matrix_sync(a[r], &As[buf][wm * 64 + r * 16][kk], 40);
#pragma unroll
            for (int f = 0; f < 2; f++) {
                wmma::fragment<wmma::matrix_b, 16, 16, 16, __half, wmma::row_major> b;
                wmma::load_matrix_sync(b, &Bs[buf][kk][wn * 32 + f * 16], 136);
#pragma unroll
                for (int r = 0; r < 4; r++) wmma::mma_sync(c[r][f], a[r], b, c[r][f]);
            }
        }
        __syncthreads();
    }

    // Epilogue: per-frag smem staging (reuse As as float scratch), fp32 -> fp16
    __syncthreads();
    float* scratch = reinterpret_cast<float*>(&As[0][0][0]) + warpId * 256;
    const int lid = tid & 31;
    const int lr  = lid >> 1;            // 0..15
    const int lc  = (lid & 1) * 8;       // 0 or 8
#pragma unroll
    for (int r = 0; r < 4; r++)
#pragma unroll
        for (int f = 0; f < 2; f++) {
            wmma::store_matrix_sync(scratch, c[r][f], 16, wmma::mem_row_major);
            __syncwarp();
            const float* src = scratch + lr * 16 + lc;
            __half2 h[4];
#pragma unroll
            for (int q = 0; q < 4; q++)
                h[q] = __floats2half2_rn(src[2 * q], src[2 * q + 1]);
            const size_t row = (size_t)(m0 + wm * 64 + r * 16 + lr);
            *(uint4*)&C[row * 256 + n0 + wn * 32 + f * 16 + lc] =
                *(uint4*)&h[0];
            __syncwarp();
        }
}

// ---------------------------------------------------------------------------
// k_out (fp16 wmma, gathered): out[n][h] = sum_c t2h[ids[n]][c] * f2h[h][c]
// A = gathered t2h rows (m,k) row-major; B = f2h (n,k) -> col_major fragment.
// BM=128, BN=128, BK=32. Warp tile 64x32. Output fp32 direct.
// ---------------------------------------------------------------------------
__global__ void k_out(const int* __restrict__ ids, float* __restrict__ out) {
    const int n0 = blockIdx.x * 128;
    const int m0 = blockIdx.y * 128;

    __shared__ __align__(16) __half As[2][128][40];    // [m][k] ld=40
    __shared__ __align__(16) __half Bs[2][128][40];    // [n][k] ld=40
    __shared__ int srow[128];

    const int tid    = threadIdx.x;
    const int warpId = tid >> 5;
    const int wm     = warpId & 1;
    const int wn     = warpId >> 1;

    if (tid < 128) srow[tid] = ids[m0 + tid];
    __syncthreads();

    wmma::fragment<wmma::accumulator, 16, 16, 16, float> c[4][2];
#pragma unroll
    for (int r = 0; r < 4; r++)
#pragma unroll
        for (int f = 0; f < 2; f++) wmma::fill_fragment(c[r][f], 0.0f);

#define STAGE_OUT(bufi, k0)                                                             \
    do {                                                                                \
        _Pragma("unroll")                                                               \
        for (int rep = 0; rep < 2; rep++) {                                             \
            int idx = tid + rep * 256;                                                  \
            int r_ = idx >> 2, c_ = (idx & 3) * 8;                                      \
            cp16(&As[bufi][r_][c_], &g_t2h[(size_t)srow[r_] * 256 + (k0) + c_]);        \
        }                                                                               \
        _Pragma("unroll")                                                               \
        for (int rep = 0; rep < 2; rep++) {                                             \
            int idx = tid + rep * 256;                                                  \
            int r_ = idx >> 2, c_ = (idx & 3) * 8;                                      \
            cp16(&Bs[bufi][r_][c_], &g_f2h[(size_t)(n0 + r_) * 256 + (k0) + c_]);       \
        }                                                                               \
        CP_COMMIT();                                                                    \
    } while (0)

    STAGE_OUT(0, 0);

    for (int it = 0; it < 8; ++it) {
        const int buf = it & 1;
        if (it < 7) { STAGE_OUT(buf ^ 1, (it + 1) * 32); CP_WAIT1(); }
        else        { CP_WAIT0(); }
        __syncthreads();

#pragma unroll
        for (int kk = 0; kk < 32; kk += 16) {
            wmma::fragment<wmma::matrix_a, 16, 16, 16, __half, wmma::row_major> a[4];
#pragma unroll
            for (int r = 0; r < 4; r++)
                wmma::load_matrix_sync(a[r], &As[buf][wm * 64 + r * 16][kk], 40);
#pragma unroll
            for (int f = 0; f < 2; f++) {
                // col_major: element (k, n_local) at base[n_local*ld + k]
                wmma::fragment<wmma::matrix_b, 16, 16, 16, __half, wmma::col_major> b;
                wmma::load_matrix_sync(b, &Bs[buf][wn * 32 + f * 16][kk], 40);
#pragma unroll
                for (int r = 0; r < 4; r++) wmma::mma_sync(c[r][f], a[r], b, c[r][f]);
            }
        }
        __syncthreads();
    }

#pragma unroll
    for (int r = 0; r < 4; r++)
#pragma unroll
        for (int f = 0; f < 2; f++)
            wmma::store_matrix_sync(
                &out[(size_t)(m0 + wm * 64 + r * 16) * 768 + n0 + wn * 32 + f * 16],
                c[r][f], 768, wmma::mem_row_major);
}

// ---------------------------------------------------------------------------
// Inputs: 0=x (unused), 1=ids, 2=core, 3=f0, 4=f1, 5=f2 ; out: 8192x768 fp32
// ---------------------------------------------------------------------------
extern "C" void kernel_launch(void* const* d_in, const int* in_sizes, int n_in,
                              void* d_out, int out_size) {
    const int*   ids  = (const int*)d_in[1];
    const float* core = (const float*)d_in[2];
    const float* f0   = (const float*)d_in[3];
    const float* f1   = (const float*)d_in[4];
    const float* f2   = (const float*)d_in[5];
    float*       out  = (float*)d_out;

    k_prep<<<192, 256>>>(f1, f2);
    {
        dim3 grid(256, 4);
        k_t1<<<grid, 256>>>(core, f0);
    }
    {
        dim3 grid(256 / 128, 768 / 128, 40);   // (n-tiles, m-tiles, i)
        k_t2<<<grid, 256>>>();
    }
    {
        dim3 grid(768 / 128, 8192 / 128);      // (n-tiles, m-tiles)
        k_out<<<grid, 256>>>(ids, out);
    }
}

// round 14
// speedup vs baseline: 4.7896x; 1.0385x over previous
#include <cuda_runtime.h>
#include <cuda_fp16.h>
#include <mma.h>
#include <cstdint>

using namespace nvcuda;

// ---------------------------------------------------------------------------
// Scratch (__device__ globals; allocation-free rule) — all fp16
// g_t1h padded to 48 rows (wmma M-pad 40->48 writes 8 garbage rows; k_t2 reads
// only rows 0..39 per slab at i*65536).
// ---------------------------------------------------------------------------
__device__ __align__(16) __half g_t1h[48 * 65536];       // [i][b*256+c], i<40 valid
__device__ __align__(16) __half g_t2h[40 * 768 * 256];   // [(i*768+j)][c]
__device__ __align__(16) __half g_f1h[768 * 256];        // [j][b]
__device__ __align__(16) __half g_f2h[768 * 256];        // [h][c]

__device__ __forceinline__ void cp16(void* s, const void* g) {
    unsigned int sa = (unsigned int)__cvta_generic_to_shared(s);
    asm volatile("cp.async.cg.shared.global [%0], [%1], 16;\n" :: "r"(sa), "l"(g));
}
#define CP_COMMIT() asm volatile("cp.async.commit_group;\n" ::: "memory")
#define CP_WAIT1()  asm volatile("cp.async.wait_group 1;\n" ::: "memory")
#define CP_WAIT0()  asm volatile("cp.async.wait_group 0;\n" ::: "memory")

// ---------------------------------------------------------------------------
// k_prep: f1, f2 -> fp16
// ---------------------------------------------------------------------------
__global__ void k_prep(const float* __restrict__ f1, const float* __restrict__ f2) {
    int idx = blockIdx.x * blockDim.x + threadIdx.x;   // 0..49151 (x4 floats)
    float4 v = ((const float4*)f1)[idx];
    __half2 a = __floats2half2_rn(v.x, v.y), b = __floats2half2_rn(v.z, v.w);
    ((__half2*)g_f1h)[idx * 2] = a; ((__half2*)g_f1h)[idx * 2 + 1] = b;
    v = ((const float4*)f2)[idx];
    a = __floats2half2_rn(v.x, v.y); b = __floats2half2_rn(v.z, v.w);
    ((__half2*)g_f2h)[idx * 2] = a; ((__half2*)g_f2h)[idx * 2 + 1] = b;
}

// ---------------------------------------------------------------------------
// k_t1 (fp16 wmma): t1(40x65536) = f0(40x40) @ core_flat(40x65536)
// M pad 40->48 (3 m16 tiles), K pad 40->48 (3 k16 steps). Core staged fp32->fp16
// in smem (single read of core). Block 128 threads, N tile = 128; grid 512.
// Output row i contiguous 65536 = t1[i][b][c] b-major, exactly k_t2's B layout.
// ---------------------------------------------------------------------------
__global__ void k_t1(const float* __restrict__ core, const float* __restrict__ f0) {
    __shared__ __align__(16) __half As[48][56];    // [m][k] ld=56 (f0, padded)
    __shared__ __align__(16) __half Bs[48][136];   // [k][n] ld=136 (core tile, padded)
    __shared__ float scratch[4][256];              // per-warp epilogue staging

    const int tid = threadIdx.x;                   // 128
    const int warpId = tid >> 5, lid = tid & 31;
    const int n0 = blockIdx.x * 128;

    // zero pads (whole As; Bs pad rows 40..47) — avoids NaN*0 in padded K range
    for (int x = tid; x < 48 * 56; x += 128) (&As[0][0])[x] = __float2half(0.0f);
    for (int x = tid; x < 8 * 136; x += 128) Bs[40 + x / 136][x % 136] = __float2half(0.0f);
    __syncthreads();

    // stage f0 (40x40 fp32 -> fp16)
    for (int x = tid; x < 1600; x += 128)
        As[x / 40][x % 40] = __float2half(f0[x]);
    // stage core tile: rows a=0..39, cols n0..n0+127 (fp32 -> fp16)
    for (int x = tid; x < 1280; x += 128) {
        int r = x >> 5, c4 = (x & 31) * 4;
        float4 v = *(const float4*)&core[(size_t)r * 65536 + n0 + c4];
        Bs[r][c4 + 0] = __float2half(v.x);
        Bs[r][c4 + 1] = __float2half(v.y);
        Bs[r][c4 + 2] = __float2half(v.z);
        Bs[r][c4 + 3] = __float2half(v.w);
    }
    __syncthreads();

    // 4 warps split N into 4 x 32; each computes 3 m-tiles x 2 n-frags
    wmma::fragment<wmma::accumulator, 16, 16, 16, float> c[3][2];
#pragma unroll
    for (int mt = 0; mt < 3; mt++)
#pragma unroll
        for (int f = 0; f < 2; f++) wmma::fill_fragment(c[mt][f], 0.0f);

#pragma unroll
    for (int kk = 0; kk < 48; kk += 16) {
        wmma::fragment<wmma::matrix_a, 16, 16, 16, __half, wmma::row_major> a[3];
#pragma unroll
        for (int mt = 0; mt < 3; mt++)
            wmma::load_matrix_sync(a[mt], &As[mt * 16][kk], 56);
#pragma unroll
        for (int f = 0; f < 2; f++) {
            wmma::fragment<wmma::matrix_b, 16, 16, 16, __half, wmma::row_major> b;
            wmma::load_matrix_sync(b, &Bs[kk][warpId * 32 + f * 16], 136);
#pragma unroll
            for (int mt = 0; mt < 3; mt++) wmma::mma_sync(c[mt][f], a[mt], b, c[mt][f]);
        }
    }

    // epilogue: fp32 frag -> fp16, rows 40..47 land in g_t1h pad rows
    float* scr = scratch[warpId];
    const int lr = lid >> 1, lc = (lid & 1) * 8;
#pragma unroll
    for (int mt = 0; mt < 3; mt++)
#pragma unroll
        for (int f = 0; f < 2; f++) {
            wmma::store_matrix_sync(scr, c[mt][f], 16, wmma::mem_row_major);
            __syncwarp();
            const float* src = scr + lr * 16 + lc;
            __half2 h[4];
#pragma unroll
            for (int q = 0; q < 4; q++)
                h[q] = __floats2half2_rn(src[2 * q], src[2 * q + 1]);
            *(uint4*)&g_t1h[(size_t)(mt * 16 + lr) * 65536 + n0 + warpId * 32 + f * 16 + lc] =
                *(uint4*)&h[0];
            __syncwarp();
        }
}

// ---------------------------------------------------------------------------
// k_t2 (fp16 wmma, cp.async pipelined): per i: t2_i (768x256) = f1 @ t1_i
// A = f1h (m,k) row-major; B = t1h_i (k,n) row-major. Output fp16.
// BM=128, BN=128, BK=32. 8 warps as 2(M) x 4(N); warp tile 64x32 (c[4][2]).
// ---------------------------------------------------------------------------
__global__ void k_t2() {
    const int n0 = blockIdx.x * 128;
    const int m0 = blockIdx.y * 128;
    const int i  = blockIdx.z;

    const __half* __restrict__ A = g_f1h;
    const __half* __restrict__ B = g_t1h + (size_t)i * 65536;
    __half* __restrict__ C = g_t2h + (size_t)i * (768 * 256);

    __shared__ __align__(16) __half As[2][128][40];    // [m][k] ld=40
    __shared__ __align__(16) __half Bs[2][32][136];    // [k][n] ld=136

    const int tid    = threadIdx.x;
    const int warpId = tid >> 5;
    const int wm     = warpId & 1;       // 0..1 -> m offset wm*64
    const int wn     = warpId >> 1;      // 0..3 -> n offset wn*32

    wmma::fragment<wmma::accumulator, 16, 16, 16, float> c[4][2];
#pragma unroll
    for (int r = 0; r < 4; r++)
#pragma unroll
        for (int f = 0; f < 2; f++) wmma::fill_fragment(c[r][f], 0.0f);

#define STAGE_T2(bufi, k0)                                                              \
    do {                                                                                \
        _Pragma("unroll")                                                               \
        for (int rep = 0; rep < 2; rep++) {                                             \
            int idx = tid + rep * 256;                                                  \
            int r_ = idx >> 2, c_ = (idx & 3) * 8;                                      \
            cp16(&As[bufi][r_][c_], &A[(size_t)(m0 + r_) * 256 + (k0) + c_]);           \
        }                                                                               \
        _Pragma("unroll")                                                               \
        for (int rep = 0; rep < 2; rep++) {                                             \
            int idx = tid + rep * 256;                                                  \
            int r_ = idx >> 4, c_ = (idx & 15) * 8;                                     \
            cp16(&Bs[bufi][r_][c_], &B[(size_t)((k0) + r_) * 256 + n0 + c_]);           \
        }                                                                               \
        CP_COMMIT();                                                                    \
    } while (0)

    STAGE_T2(0, 0);

    for (int it = 0; it < 8; ++it) {
        const int buf = it & 1;
        if (it < 7) { STAGE_T2(buf ^ 1, (it + 1) * 32); CP_WAIT1(); }
        else        { CP_WAIT0(); }
        __syncthreads();

#pragma unroll
        for (int kk = 0; kk < 32; kk += 16) {
            wmma::fragment<wmma::matrix_a, 16, 16, 16, __half, wmma::row_major> a[4];
#pragma unroll
            for (int r = 0; r < 4; r++)
                wmma::load_matrix_sync(a[r], &As[buf][wm * 64 + r * 16][kk], 40);
#pragma unroll
            for (int f = 0; f < 2; f++) {
                wmma::fragment<wmma::matrix_b, 16, 16, 16, __half, wmma::row_major> b;
                wmma::load_matrix_sync(b, &Bs[buf][kk][wn * 32 + f * 16], 136);
#pragma unroll
                for (int r = 0; r < 4; r++) wmma::mma_sync(c[r][f], a[r], b, c[r][f]);
            }
        }
        __syncthreads();
    }

    // Epilogue: per-frag smem staging (reuse As as float scratch), fp32 -> fp16
    __syncthreads();
    float* scratch = reinterpret_cast<float*>(&As[0][0][0]) + warpId * 256;
    const int lid = tid & 31;
    const int lr  = lid >> 1;            // 0..15
    const int lc  = (lid & 1) * 8;       // 0 or 8
#pragma unroll
    for (int r = 0; r < 4; r++)
#pragma unroll
        for (int f = 0; f < 2; f++) {
            wmma::store_matrix_sync(scratch, c[r][f], 16, wmma::mem_row_major);
            __syncwarp();
            const float* src = scratch + lr * 16 + lc;
            __half2 h[4];
#pragma unroll
            for (int q = 0; q < 4; q++)
                h[q] = __floats2half2_rn(src[2 * q], src[2 * q + 1]);
            const size_t row = (size_t)(m0 + wm * 64 + r * 16 + lr);
            *(uint4*)&C[row * 256 + n0 + wn * 32 + f * 16 + lc] =
                *(uint4*)&h[0];
            __syncwarp();
        }
}

// ---------------------------------------------------------------------------
// k_out (fp16 wmma, gathered): out[n][h] = sum_c t2h[ids[n]][c] * f2h[h][c]
// A = gathered t2h rows (m,k) row-major; B = f2h (n,k) -> col_major fragment.
// BM=128, BN=128, BK=32. Warp tile 64x32. Output fp32 direct.
// ---------------------------------------------------------------------------
__global__ void k_out(const int* __restrict__ ids, float* __restrict__ out) {
    const int n0 = blockIdx.x * 128;
    const int m0 = blockIdx.y * 128;

    __shared__ __align__(16) __half As[2][128][40];    // [m][k] ld=40
    __shared__ __align__(16) __half Bs[2][128][40];    // [n][k] ld=40
    __shared__ int srow[128];

    const int tid    = threadIdx.x;
    const int warpId = tid >> 5;
    const int wm     = warpId & 1;
    const int wn     = warpId >> 1;

    if (tid < 128) srow[tid] = ids[m0 + tid];
    __syncthreads();

    wmma::fragment<wmma::accumulator, 16, 16, 16, float> c[4][2];
#pragma unroll
    for (int r = 0; r < 4; r++)
#pragma unroll
        for (int f = 0; f < 2; f++) wmma::fill_fragment(c[r][f], 0.0f);

#define STAGE_OUT(bufi, k0)                                                             \
    do {                                                                                \
        _Pragma("unroll")                                                               \
        for (int rep = 0; rep < 2; rep++) {                                             \
            int idx = tid + rep * 256;                                                  \
            int r_ = idx >> 2, c_ = (idx & 3) * 8;                                      \
            cp16(&As[bufi][r_][c_], &g_t2h[(size_t)srow[r_] * 256 + (k0) + c_]);        \
        }                                                                               \
        _Pragma("unroll")                                                               \
        for (int rep = 0; rep < 2; rep++) {                                             \
            int idx = tid + rep * 256;                                                  \
            int r_ = idx >> 2, c_ = (idx & 3) * 8;                                      \
            cp16(&Bs[bufi][r_][c_], &g_f2h[(size_t)(n0 + r_) * 256 + (k0) + c_]);       \
        }                                                                               \
        CP_COMMIT();                                                                    \
    } while (0)

    STAGE_OUT(0, 0);

    for (int it = 0; it < 8; ++it) {
        const int buf = it & 1;
        if (it < 7) { STAGE_OUT(buf ^ 1, (it + 1) * 32); CP_WAIT1(); }
        else        { CP_WAIT0(); }
        __syncthreads();

#pragma unroll
        for (int kk = 0; kk < 32; kk += 16) {
            wmma::fragment<wmma::matrix_a, 16, 16, 16, __half, wmma::row_major> a[4];
#pragma unroll
            for (int r = 0; r < 4; r++)
                wmma::load_matrix_sync(a[r], &As[buf][wm * 64 + r * 16][kk], 40);
#pragma unroll
            for (int f = 0; f < 2; f++) {
                // col_major: element (k, n_local) at base[n_local*ld + k]
                wmma::fragment<wmma::matrix_b, 16, 16, 16, __half, wmma::col_major> b;
                wmma::load_matrix_sync(b, &Bs[buf][wn * 32 + f * 16][kk], 40);
#pragma unroll
                for (int r = 0; r < 4; r++) wmma::mma_sync(c[r][f], a[r], b, c[r][f]);
            }
        }
        __syncthreads();
    }

#pragma unroll
    for (int r = 0; r < 4; r++)
#pragma unroll
        for (int f = 0; f < 2; f++)
            wmma::store_matrix_sync(
                &out[(size_t)(m0 + wm * 64 + r * 16) * 768 + n0 + wn * 32 + f * 16],
                c[r][f], 768, wmma::mem_row_major);
}

// ---------------------------------------------------------------------------
// Inputs: 0=x (unused), 1=ids, 2=core, 3=f0, 4=f1, 5=f2 ; out: 8192x768 fp32
// ---------------------------------------------------------------------------
extern "C" void kernel_launch(void* const* d_in, const int* in_sizes, int n_in,
                              void* d_out, int out_size) {
    const int*   ids  = (const int*)d_in[1];
    const float* core = (const float*)d_in[2];
    const float* f0   = (const float*)d_in[3];
    const float* f1   = (const float*)d_in[4];
    const float* f2   = (const float*)d_in[5];
    float*       out  = (float*)d_out;

    k_prep<<<192, 256>>>(f1, f2);
    k_t1<<<512, 128>>>(core, f0);              // 512 n-tiles of 128
    {
        dim3 grid(256 / 128, 768 / 128, 40);   // (n-tiles, m-tiles, i)
        k_t2<<<grid, 256>>>();
    }
    {
        dim3 grid(768 / 128, 8192 / 128);      // (n-tiles, m-tiles)
        k_out<<<grid, 256>>>(ids, out);
    }
}